// round 12
// baseline (speedup 1.0000x reference)
#include <cuda_runtime.h>
#include <math.h>

#define UNROLL 8
#define TPB 256

// 3 rows x 4 cols of the affine transform (row 3 is [0,0,0,1], implicit).
__device__ float4 g_trans[3];

// ---------------------------------------------------------------------------
// Setup kernel (1 thread): M[i][j] = scale[j] * (se3_exp_rot(tau) @ R)[i][j]
// (column scaling per numpy broadcast over last axis), M[i][3] = T[i] + dt[i].
// ---------------------------------------------------------------------------
__global__ void setup_kernel(const float* __restrict__ rot_delta,
                             const float* __restrict__ trans_delta,
                             const float* __restrict__ scale,
                             const float* __restrict__ Rin,
                             const float* __restrict__ Tin)
{
    float tx = rot_delta[0], ty = rot_delta[1], tz = rot_delta[2];
    float rx = trans_delta[0], ry = trans_delta[1], rz = trans_delta[2];

    float angle = sqrtf(tx * tx + ty * ty + tz * tz);
    bool small = angle < 1e-5f;
    float a = small ? 1.0f : angle;

    float sa = sinf(a);
    float ca = cosf(a);
    float A = small ? 1.0f : (sa / a);
    float B = small ? 0.5f : ((1.0f - ca) / (a * a));
    float C = small ? (1.0f / 6.0f) : ((a - sa) / (a * a * a));

    float W[9] = { 0.0f, -tz,  ty,
                   tz,  0.0f, -tx,
                  -ty,   tx, 0.0f };
    float W2[9];
    #pragma unroll
    for (int i = 0; i < 3; i++)
        #pragma unroll
        for (int j = 0; j < 3; j++) {
            float s = 0.0f;
            #pragma unroll
            for (int k = 0; k < 3; k++) s += W[i * 3 + k] * W[k * 3 + j];
            W2[i * 3 + j] = s;
        }

    float dR[9], Vm[9];
    #pragma unroll
    for (int i = 0; i < 9; i++) {
        float I = (i % 4 == 0) ? 1.0f : 0.0f;
        dR[i] = I + A * W[i] + B * W2[i];
        Vm[i] = I + B * W[i] + C * W2[i];
    }

    float dt[3];
    #pragma unroll
    for (int i = 0; i < 3; i++)
        dt[i] = Vm[i * 3 + 0] * rx + Vm[i * 3 + 1] * ry + Vm[i * 3 + 2] * rz;

    #pragma unroll
    for (int i = 0; i < 3; i++) {
        float row[4];
        #pragma unroll
        for (int j = 0; j < 3; j++) {
            float s = 0.0f;
            #pragma unroll
            for (int k = 0; k < 3; k++) s += dR[i * 3 + k] * Rin[k * 3 + j];
            row[j] = scale[j] * s;
        }
        row[3] = Tin[i] + dt[i];
        g_trans[i] = make_float4(row[0], row[1], row[2], row[3]);
    }
}

// ---------------------------------------------------------------------------
// Apply kernel: y = M @ x, 8 coalesced float4s per thread, streaming
// (evict-first) hints — zero reuse. Matrix rows are uniform L1/L2
// broadcast hits; no trig, no shared mem, no __syncthreads in hot path.
// ---------------------------------------------------------------------------
__global__ void __launch_bounds__(TPB) apply_kernel(const float4* __restrict__ x,
                                                    float4* __restrict__ y,
                                                    int n4)
{
    float4 r0 = g_trans[0];
    float4 r1 = g_trans[1];
    float4 r2 = g_trans[2];

    int base = blockIdx.x * (TPB * UNROLL) + threadIdx.x;

    if (base + (UNROLL - 1) * TPB < n4) {
        // Fast path: whole tile in range (all blocks when N % (TPB*UNROLL)==0).
        float4 v[UNROLL];
        #pragma unroll
        for (int u = 0; u < UNROLL; u++)
            v[u] = __ldcs(&x[base + u * TPB]);

        #pragma unroll
        for (int u = 0; u < UNROLL; u++) {
            float4 p = v[u];
            float4 o;
            o.x = fmaf(r0.x, p.x, fmaf(r0.y, p.y, fmaf(r0.z, p.z, r0.w * p.w)));
            o.y = fmaf(r1.x, p.x, fmaf(r1.y, p.y, fmaf(r1.z, p.z, r1.w * p.w)));
            o.z = fmaf(r2.x, p.x, fmaf(r2.y, p.y, fmaf(r2.z, p.z, r2.w * p.w)));
            o.w = p.w;
            __stcs(&y[base + u * TPB], o);
        }
    } else {
        // Tail path: per-element bounds check.
        #pragma unroll
        for (int u = 0; u < UNROLL; u++) {
            int i = base + u * TPB;
            if (i < n4) {
                float4 p = __ldcs(&x[i]);
                float4 o;
                o.x = fmaf(r0.x, p.x, fmaf(r0.y, p.y, fmaf(r0.z, p.z, r0.w * p.w)));
                o.y = fmaf(r1.x, p.x, fmaf(r1.y, p.y, fmaf(r1.z, p.z, r1.w * p.w)));
                o.z = fmaf(r2.x, p.x, fmaf(r2.y, p.y, fmaf(r2.z, p.z, r2.w * p.w)));
                o.w = p.w;
                __stcs(&y[i], o);
            }
        }
    }
}

extern "C" void kernel_launch(void* const* d_in, const int* in_sizes, int n_in,
                              void* d_out, int out_size)
{
    const float* x          = (const float*)d_in[0];   // (N,4)
    const float* rot_delta  = (const float*)d_in[1];   // (3,)
    const float* trans_delta= (const float*)d_in[2];   // (3,)
    const float* scale      = (const float*)d_in[3];   // (3,)
    const float* R          = (const float*)d_in[4];   // (3,3)
    const float* T          = (const float*)d_in[5];   // (3,)
    float* out = (float*)d_out;

    int n4 = in_sizes[0] / 4;   // number of points (float4 elements)

    setup_kernel<<<1, 1>>>(rot_delta, trans_delta, scale, R, T);

    int elems_per_block = TPB * UNROLL;
    int blocks = (n4 + elems_per_block - 1) / elems_per_block;
    apply_kernel<<<blocks, TPB>>>((const float4*)x, (float4*)out, n4);
}

// round 16
// speedup vs baseline: 1.0206x; 1.0206x over previous
#include <cuda_runtime.h>
#include <math.h>

#define UNROLL 8
#define TPB 256

// ---------------------------------------------------------------------------
// Fused kernel: thread 0 of each block computes the 3x4 affine transform
//   M[i][j] = scale[j] * (se3_exp_rot(tau) @ R)[i][j],  M[i][3] = T[i] + dt[i]
// (column scaling per numpy broadcast over last axis), then all threads
// stream y = M @ x with 8 coalesced float4s per thread using streaming
// (evict-first) cache hints — data has zero reuse.
//
// FROZEN at the HBM R/W-turnaround ceiling (~6.25-6.4 TB/s, 79-81% of spec):
// measured invariant across UNROLL {1,4,8}, occupancy 40-75%, cache hints,
// prologue weight (split-kernel: identical kernel time, +1.5us launch cost),
// and persistence (single-wave persistent grid: 12% SLOWER, DRAM 74%).
// Full oversubscribed grid + single launch is the best measured structure.
// ---------------------------------------------------------------------------
__global__ void __launch_bounds__(TPB) fused_kernel(
    const float4* __restrict__ x,
    float4* __restrict__ y,
    const float* __restrict__ rot_delta,
    const float* __restrict__ trans_delta,
    const float* __restrict__ scale,
    const float* __restrict__ Rin,
    const float* __restrict__ Tin,
    int n4)
{
    __shared__ float4 sM[3];

    if (threadIdx.x == 0) {
        float tx = rot_delta[0], ty = rot_delta[1], tz = rot_delta[2];
        float rx = trans_delta[0], ry = trans_delta[1], rz = trans_delta[2];

        float angle = sqrtf(tx * tx + ty * ty + tz * tz);
        bool small = angle < 1e-5f;
        float a = small ? 1.0f : angle;

        float sa = sinf(a);
        float ca = cosf(a);
        float A = small ? 1.0f : (sa / a);
        float B = small ? 0.5f : ((1.0f - ca) / (a * a));
        float C = small ? (1.0f / 6.0f) : ((a - sa) / (a * a * a));

        float W[9] = { 0.0f, -tz,  ty,
                       tz,  0.0f, -tx,
                      -ty,   tx, 0.0f };
        float W2[9];
        #pragma unroll
        for (int i = 0; i < 3; i++)
            #pragma unroll
            for (int j = 0; j < 3; j++) {
                float s = 0.0f;
                #pragma unroll
                for (int k = 0; k < 3; k++) s += W[i * 3 + k] * W[k * 3 + j];
                W2[i * 3 + j] = s;
            }

        float dR[9], Vm[9];
        #pragma unroll
        for (int i = 0; i < 9; i++) {
            float I = (i % 4 == 0) ? 1.0f : 0.0f;
            dR[i] = I + A * W[i] + B * W2[i];
            Vm[i] = I + B * W[i] + C * W2[i];
        }

        float dt[3];
        #pragma unroll
        for (int i = 0; i < 3; i++)
            dt[i] = Vm[i * 3 + 0] * rx + Vm[i * 3 + 1] * ry + Vm[i * 3 + 2] * rz;

        #pragma unroll
        for (int i = 0; i < 3; i++) {
            float row[4];
            #pragma unroll
            for (int j = 0; j < 3; j++) {
                float s = 0.0f;
                #pragma unroll
                for (int k = 0; k < 3; k++) s += dR[i * 3 + k] * Rin[k * 3 + j];
                row[j] = scale[j] * s;
            }
            row[3] = Tin[i] + dt[i];
            sM[i] = make_float4(row[0], row[1], row[2], row[3]);
        }
    }
    __syncthreads();

    float4 r0 = sM[0];
    float4 r1 = sM[1];
    float4 r2 = sM[2];

    int base = blockIdx.x * (TPB * UNROLL) + threadIdx.x;

    if (base + (UNROLL - 1) * TPB < n4) {
        // Fast path: whole tile in range (all blocks when N % (TPB*UNROLL)==0).
        float4 v[UNROLL];
        #pragma unroll
        for (int u = 0; u < UNROLL; u++)
            v[u] = __ldcs(&x[base + u * TPB]);

        #pragma unroll
        for (int u = 0; u < UNROLL; u++) {
            float4 p = v[u];
            float4 o;
            o.x = fmaf(r0.x, p.x, fmaf(r0.y, p.y, fmaf(r0.z, p.z, r0.w * p.w)));
            o.y = fmaf(r1.x, p.x, fmaf(r1.y, p.y, fmaf(r1.z, p.z, r1.w * p.w)));
            o.z = fmaf(r2.x, p.x, fmaf(r2.y, p.y, fmaf(r2.z, p.z, r2.w * p.w)));
            o.w = p.w;
            __stcs(&y[base + u * TPB], o);
        }
    } else {
        // Tail path: per-element bounds check.
        #pragma unroll
        for (int u = 0; u < UNROLL; u++) {
            int i = base + u * TPB;
            if (i < n4) {
                float4 p = __ldcs(&x[i]);
                float4 o;
                o.x = fmaf(r0.x, p.x, fmaf(r0.y, p.y, fmaf(r0.z, p.z, r0.w * p.w)));
                o.y = fmaf(r1.x, p.x, fmaf(r1.y, p.y, fmaf(r1.z, p.z, r1.w * p.w)));
                o.z = fmaf(r2.x, p.x, fmaf(r2.y, p.y, fmaf(r2.z, p.z, r2.w * p.w)));
                o.w = p.w;
                __stcs(&y[i], o);
            }
        }
    }
}

extern "C" void kernel_launch(void* const* d_in, const int* in_sizes, int n_in,
                              void* d_out, int out_size)
{
    const float* x          = (const float*)d_in[0];   // (N,4)
    const float* rot_delta  = (const float*)d_in[1];   // (3,)
    const float* trans_delta= (const float*)d_in[2];   // (3,)
    const float* scale      = (const float*)d_in[3];   // (3,)
    const float* R          = (const float*)d_in[4];   // (3,3)
    const float* T          = (const float*)d_in[5];   // (3,)
    float* out = (float*)d_out;

    int n4 = in_sizes[0] / 4;   // number of points (float4 elements)

    int elems_per_block = TPB * UNROLL;
    int blocks = (n4 + elems_per_block - 1) / elems_per_block;

    fused_kernel<<<blocks, TPB>>>((const float4*)x, (float4*)out,
                                  rot_delta, trans_delta, scale, R, T, n4);
}

// round 17
// speedup vs baseline: 1.0214x; 1.0008x over previous
#include <cuda_runtime.h>
#include <math.h>

#define UNROLL 8
#define TPB 256

// ---------------------------------------------------------------------------
// Fused kernel: thread 0 of each block computes the 3x4 affine transform
//   M[i][j] = scale[j] * (se3_exp_rot(tau) @ R)[i][j],  M[i][3] = T[i] + dt[i]
// (column scaling per numpy broadcast over last axis), then all threads
// stream y = M @ x with 8 coalesced float4s per thread using streaming
// (evict-first) cache hints — data has zero reuse.
//
// FROZEN at the HBM R/W-turnaround ceiling (~6.25-6.4 TB/s, 79-81% of spec):
// measured invariant across UNROLL {1,4,8}, occupancy 40-75%, cache hints,
// prologue weight (split-kernel: identical kernel time, +1.5us launch cost),
// and persistence (single-wave persistent grid: 12% SLOWER, DRAM 74%).
// Full oversubscribed grid + single launch is the best measured structure.
// Confirmed over 4 independent runs: 82.4-83.3us total, sigma ~0.4us.
// ---------------------------------------------------------------------------
__global__ void __launch_bounds__(TPB) fused_kernel(
    const float4* __restrict__ x,
    float4* __restrict__ y,
    const float* __restrict__ rot_delta,
    const float* __restrict__ trans_delta,
    const float* __restrict__ scale,
    const float* __restrict__ Rin,
    const float* __restrict__ Tin,
    int n4)
{
    __shared__ float4 sM[3];

    if (threadIdx.x == 0) {
        float tx = rot_delta[0], ty = rot_delta[1], tz = rot_delta[2];
        float rx = trans_delta[0], ry = trans_delta[1], rz = trans_delta[2];

        float angle = sqrtf(tx * tx + ty * ty + tz * tz);
        bool small = angle < 1e-5f;
        float a = small ? 1.0f : angle;

        float sa = sinf(a);
        float ca = cosf(a);
        float A = small ? 1.0f : (sa / a);
        float B = small ? 0.5f : ((1.0f - ca) / (a * a));
        float C = small ? (1.0f / 6.0f) : ((a - sa) / (a * a * a));

        float W[9] = { 0.0f, -tz,  ty,
                       tz,  0.0f, -tx,
                      -ty,   tx, 0.0f };
        float W2[9];
        #pragma unroll
        for (int i = 0; i < 3; i++)
            #pragma unroll
            for (int j = 0; j < 3; j++) {
                float s = 0.0f;
                #pragma unroll
                for (int k = 0; k < 3; k++) s += W[i * 3 + k] * W[k * 3 + j];
                W2[i * 3 + j] = s;
            }

        float dR[9], Vm[9];
        #pragma unroll
        for (int i = 0; i < 9; i++) {
            float I = (i % 4 == 0) ? 1.0f : 0.0f;
            dR[i] = I + A * W[i] + B * W2[i];
            Vm[i] = I + B * W[i] + C * W2[i];
        }

        float dt[3];
        #pragma unroll
        for (int i = 0; i < 3; i++)
            dt[i] = Vm[i * 3 + 0] * rx + Vm[i * 3 + 1] * ry + Vm[i * 3 + 2] * rz;

        #pragma unroll
        for (int i = 0; i < 3; i++) {
            float row[4];
            #pragma unroll
            for (int j = 0; j < 3; j++) {
                float s = 0.0f;
                #pragma unroll
                for (int k = 0; k < 3; k++) s += dR[i * 3 + k] * Rin[k * 3 + j];
                row[j] = scale[j] * s;
            }
            row[3] = Tin[i] + dt[i];
            sM[i] = make_float4(row[0], row[1], row[2], row[3]);
        }
    }
    __syncthreads();

    float4 r0 = sM[0];
    float4 r1 = sM[1];
    float4 r2 = sM[2];

    int base = blockIdx.x * (TPB * UNROLL) + threadIdx.x;

    if (base + (UNROLL - 1) * TPB < n4) {
        // Fast path: whole tile in range (all blocks when N % (TPB*UNROLL)==0).
        float4 v[UNROLL];
        #pragma unroll
        for (int u = 0; u < UNROLL; u++)
            v[u] = __ldcs(&x[base + u * TPB]);

        #pragma unroll
        for (int u = 0; u < UNROLL; u++) {
            float4 p = v[u];
            float4 o;
            o.x = fmaf(r0.x, p.x, fmaf(r0.y, p.y, fmaf(r0.z, p.z, r0.w * p.w)));
            o.y = fmaf(r1.x, p.x, fmaf(r1.y, p.y, fmaf(r1.z, p.z, r1.w * p.w)));
            o.z = fmaf(r2.x, p.x, fmaf(r2.y, p.y, fmaf(r2.z, p.z, r2.w * p.w)));
            o.w = p.w;
            __stcs(&y[base + u * TPB], o);
        }
    } else {
        // Tail path: per-element bounds check.
        #pragma unroll
        for (int u = 0; u < UNROLL; u++) {
            int i = base + u * TPB;
            if (i < n4) {
                float4 p = __ldcs(&x[i]);
                float4 o;
                o.x = fmaf(r0.x, p.x, fmaf(r0.y, p.y, fmaf(r0.z, p.z, r0.w * p.w)));
                o.y = fmaf(r1.x, p.x, fmaf(r1.y, p.y, fmaf(r1.z, p.z, r1.w * p.w)));
                o.z = fmaf(r2.x, p.x, fmaf(r2.y, p.y, fmaf(r2.z, p.z, r2.w * p.w)));
                o.w = p.w;
                __stcs(&y[i], o);
            }
        }
    }
}

extern "C" void kernel_launch(void* const* d_in, const int* in_sizes, int n_in,
                              void* d_out, int out_size)
{
    const float* x          = (const float*)d_in[0];   // (N,4)
    const float* rot_delta  = (const float*)d_in[1];   // (3,)
    const float* trans_delta= (const float*)d_in[2];   // (3,)
    const float* scale      = (const float*)d_in[3];   // (3,)
    const float* R          = (const float*)d_in[4];   // (3,3)
    const float* T          = (const float*)d_in[5];   // (3,)
    float* out = (float*)d_out;

    int n4 = in_sizes[0] / 4;   // number of points (float4 elements)

    int elems_per_block = TPB * UNROLL;
    int blocks = (n4 + elems_per_block - 1) / elems_per_block;

    fused_kernel<<<blocks, TPB>>>((const float4*)x, (float4*)out,
                                  rot_delta, trans_delta, scale, R, T, n4);
}